// round 9
// baseline (speedup 1.0000x reference)
#include <cuda_runtime.h>
#include <cstdint>

#define D_DIM   768
#define K_CL    16
#define TPB     96          // 3 warps; TPB*EPT = D_DIM
#define EPT     8           // elements per thread (2 x 16B)
#define RR      8           // rows per block (4 row-pairs)
#define NVAL    18          // 16 dots + sum + sumsq
#define NCOL    24          // partial cols after 4-lane pre-reduce (96/4)
#define PSU     25          // plane stride in u64 (200B: 2-way max on stage-2 reads)

typedef unsigned long long u64;

__device__ float g_c2[K_CL];

// ---- packed f32x2 helpers (sm_103a FFMA2 path; ptxas won't auto-fuse) ----
__device__ __forceinline__ u64 pack2(float lo, float hi) {
    u64 d; asm("mov.b64 %0, {%1, %2};" : "=l"(d) : "f"(lo), "f"(hi)); return d;
}
__device__ __forceinline__ float2 unpk(u64 v) {
    float2 r; asm("mov.b64 {%0, %1}, %2;" : "=f"(r.x), "=f"(r.y) : "l"(v)); return r;
}
__device__ __forceinline__ u64 fma2(u64 a, u64 b, u64 c) {
    u64 d; asm("fma.rn.f32x2 %0, %1, %2, %3;" : "=l"(d) : "l"(a), "l"(b), "l"(c)); return d;
}
__device__ __forceinline__ u64 mul2(u64 a, u64 b) {
    u64 d; asm("mul.rn.f32x2 %0, %1, %2;" : "=l"(d) : "l"(a), "l"(b)); return d;
}
__device__ __forceinline__ u64 add2(u64 a, u64 b) {
    u64 d; asm("add.rn.f32x2 %0, %1, %2;" : "=l"(d) : "l"(a), "l"(b)); return d;
}

// Precompute ||c_k||^2 once per launch sequence. 16 warps, one per centroid.
__global__ void c2_kernel(const float* __restrict__ cen) {
    int k = threadIdx.x >> 5;
    int lane = threadIdx.x & 31;
    float s = 0.f;
    #pragma unroll
    for (int i = 0; i < D_DIM / 32; i++) {
        float v = cen[k * D_DIM + lane + i * 32];
        s = fmaf(v, v, s);
    }
    #pragma unroll
    for (int o = 16; o > 0; o >>= 1) s += __shfl_xor_sync(0xffffffffu, s, o);
    if (lane == 0) g_c2[k] = s;
}

__global__ __launch_bounds__(TPB, 6) void sln_kernel(
    const float* __restrict__ x, const float* __restrict__ wts,
    const float* __restrict__ bia, const float* __restrict__ cen,
    float* __restrict__ out, float* __restrict__ bkt, int write_bkt)
{
    __shared__ u64 part[(RR / 2) * NVAL * PSU];   // 14.4 KB, u64 = packed row-pair
    __shared__ float tot[RR][NVAL + 2];
    __shared__ float c2s[K_CL];

    const int u = threadIdx.x;
    const int lane = u & 31;
    const int col = u >> 2;                  // 0..23 after 4-lane pre-reduce
    const long long base_row = (long long)blockIdx.x * RR;

    if (u < K_CL) c2s[u] = g_c2[u];

    // ---- load x: 8 rows x 8 floats/thread (2 x LDG.128), sum/sq reduced per row-pair ----
    u64 xp[RR][4];
    #pragma unroll
    for (int rp = 0; rp < RR / 2; rp++) {
        float sm2[2], sq2[2];
        #pragma unroll
        for (int h = 0; h < 2; h++) {
            int r = 2 * rp + h;
            const ulonglong2* xr = (const ulonglong2*)(x + (base_row + r) * D_DIM + u * EPT);
            ulonglong2 A = xr[0], B = xr[1];
            xp[r][0] = A.x; xp[r][1] = A.y; xp[r][2] = B.x; xp[r][3] = B.y;
            u64 s2 = add2(add2(A.x, A.y), add2(B.x, B.y));
            u64 q2 = mul2(A.x, A.x);
            q2 = fma2(A.y, A.y, q2);
            q2 = fma2(B.x, B.x, q2);
            q2 = fma2(B.y, B.y, q2);
            float2 ts = unpk(s2), tq = unpk(q2);
            sm2[h] = ts.x + ts.y;
            sq2[h] = tq.x + tq.y;
        }
        u64 sp = pack2(sm2[0], sm2[1]);
        u64 qp = pack2(sq2[0], sq2[1]);
        sp = add2(sp, __shfl_down_sync(0xffffffffu, sp, 1));
        sp = add2(sp, __shfl_down_sync(0xffffffffu, sp, 2));
        qp = add2(qp, __shfl_down_sync(0xffffffffu, qp, 1));
        qp = add2(qp, __shfl_down_sync(0xffffffffu, qp, 2));
        if ((lane & 3) == 0) {
            part[(rp * NVAL + 16) * PSU + col] = sp;   // u64 = {row even, row odd}
            part[(rp * NVAL + 17) * PSU + col] = qp;
        }
    }

    // ---- 16 centroid dots; centroid chunk loaded once (2 LDG.128), reused for 8 rows ----
    #pragma unroll
    for (int k = 0; k < K_CL; k++) {
        const ulonglong2* cr = (const ulonglong2*)(cen + k * D_DIM + u * EPT);
        ulonglong2 CA = cr[0], CB = cr[1];
        #pragma unroll
        for (int rp = 0; rp < RR / 2; rp++) {
            u64 a0 = mul2(xp[2 * rp][0], CA.x);
            a0 = fma2(xp[2 * rp][1], CA.y, a0);
            a0 = fma2(xp[2 * rp][2], CB.x, a0);
            a0 = fma2(xp[2 * rp][3], CB.y, a0);
            u64 a1 = mul2(xp[2 * rp + 1][0], CA.x);
            a1 = fma2(xp[2 * rp + 1][1], CA.y, a1);
            a1 = fma2(xp[2 * rp + 1][2], CB.x, a1);
            a1 = fma2(xp[2 * rp + 1][3], CB.y, a1);
            float2 t0 = unpk(a0), t1 = unpk(a1);
            u64 dp = pack2(t0.x + t0.y, t1.x + t1.y);
            dp = add2(dp, __shfl_down_sync(0xffffffffu, dp, 1));
            dp = add2(dp, __shfl_down_sync(0xffffffffu, dp, 2));
            if ((lane & 3) == 0) part[(rp * NVAL + k) * PSU + col] = dp;  // 1 STS.64, 6 lanes
        }
    }
    __syncthreads();

    // ---- stage 2: 72 jobs (18 vals x 4 row-pairs), each sums 24 u64 (packed adds) ----
    if (u < (RR / 2) * NVAL) {
        int rp = u / NVAL, val = u % NVAL;
        const u64* p = part + (rp * NVAL + val) * PSU;
        u64 acc0 = p[0], acc1 = p[1];
        #pragma unroll
        for (int i = 2; i < NCOL; i += 2) {
            acc0 = add2(acc0, p[i]);
            acc1 = add2(acc1, p[i + 1]);
        }
        float2 t = unpk(add2(acc0, acc1));
        tot[2 * rp][val] = t.x;
        tot[2 * rp + 1][val] = t.y;
    }
    __syncthreads();

    // ---- epilogue: per-row stats + argmin from tot (broadcast LDS), packed affine ----
    #pragma unroll
    for (int r = 0; r < RR; r++) {
        float s = tot[r][16], q = tot[r][17];
        float m = s * (1.0f / D_DIM);
        float var = q * (1.0f / D_DIM) - m * m;
        float rstd = rsqrtf(var + 1e-5f);
        float best = 3.4e38f; int sel = 0;
        #pragma unroll
        for (int k = 0; k < K_CL; k++) {
            float dist = q - 2.0f * tot[r][k] + c2s[k];   // same formula as reference
            if (dist < best) { best = dist; sel = k; }     // strict < = first-min tie-break
        }

        const ulonglong2* wr = (const ulonglong2*)(wts + sel * D_DIM + u * EPT);
        const ulonglong2* br = (const ulonglong2*)(bia + sel * D_DIM + u * EPT);
        ulonglong2 W0 = wr[0], W1 = wr[1];
        ulonglong2 B0 = br[0], B1 = br[1];
        u64 nm = pack2(-m, -m);
        u64 rs = pack2(rstd, rstd);
        u64 o0 = fma2(mul2(add2(xp[r][0], nm), rs), W0.x, B0.x);
        u64 o1 = fma2(mul2(add2(xp[r][1], nm), rs), W0.y, B0.y);
        u64 o2 = fma2(mul2(add2(xp[r][2], nm), rs), W1.x, B1.x);
        u64 o3 = fma2(mul2(add2(xp[r][3], nm), rs), W1.y, B1.y);
        ulonglong2* orow = (ulonglong2*)(out + (base_row + r) * D_DIM + u * EPT);
        orow[0] = make_ulonglong2(o0, o1);
        orow[1] = make_ulonglong2(o2, o3);

        if (write_bkt && u == 0) bkt[base_row + r] = (float)sel;
    }
}

extern "C" void kernel_launch(void* const* d_in, const int* in_sizes, int n_in,
                              void* d_out, int out_size) {
    const float* x = (const float*)d_in[0];   // [B,S,D] f32
    const float* w = (const float*)d_in[1];   // [K,D]
    const float* b = (const float*)d_in[2];   // [K,D]
    const float* c = (const float*)d_in[3];   // [K,D]
    float* out = (float*)d_out;

    int rows = in_sizes[0] / D_DIM;           // 32768
    int wb = (out_size >= rows * D_DIM + rows) ? 1 : 0;
    float* bkt = out + (size_t)rows * D_DIM;

    c2_kernel<<<1, 512>>>(c);
    sln_kernel<<<rows / RR, TPB>>>(x, w, b, c, out, bkt, wb);
}

// round 10
// speedup vs baseline: 1.2240x; 1.2240x over previous
#include <cuda_runtime.h>
#include <cstdint>

#define D_DIM 768
#define K_CL  16
#define RR    4           // rows per warp (= per block)
#define NJ    6           // float4 chunks per lane per row: lane owns 24 floats

typedef unsigned long long u64;

__device__ float g_c2[K_CL];

// ---- packed f32x2 helpers (sm_103a FFMA2 path; ptxas won't auto-fuse) ----
__device__ __forceinline__ u64 pack2(float lo, float hi) {
    u64 d; asm("mov.b64 %0, {%1, %2};" : "=l"(d) : "f"(lo), "f"(hi)); return d;
}
__device__ __forceinline__ float2 unpk(u64 v) {
    float2 r; asm("mov.b64 {%0, %1}, %2;" : "=f"(r.x), "=f"(r.y) : "l"(v)); return r;
}
__device__ __forceinline__ u64 fma2(u64 a, u64 b, u64 c) {
    u64 d; asm("fma.rn.f32x2 %0, %1, %2, %3;" : "=l"(d) : "l"(a), "l"(b), "l"(c)); return d;
}
__device__ __forceinline__ u64 mul2(u64 a, u64 b) {
    u64 d; asm("mul.rn.f32x2 %0, %1, %2;" : "=l"(d) : "l"(a), "l"(b)); return d;
}
__device__ __forceinline__ u64 add2(u64 a, u64 b) {
    u64 d; asm("add.rn.f32x2 %0, %1, %2;" : "=l"(d) : "l"(a), "l"(b)); return d;
}

// Precompute ||c_k||^2 once per launch sequence. 16 warps, one per centroid.
__global__ void c2_kernel(const float* __restrict__ cen) {
    int k = threadIdx.x >> 5;
    int lane = threadIdx.x & 31;
    float s = 0.f;
    #pragma unroll
    for (int i = 0; i < D_DIM / 32; i++) {
        float v = cen[k * D_DIM + lane + i * 32];
        s = fmaf(v, v, s);
    }
    #pragma unroll
    for (int o = 16; o > 0; o >>= 1) s += __shfl_xor_sync(0xffffffffu, s, o);
    if (lane == 0) g_c2[k] = s;
}

__global__ __launch_bounds__(32) void sln_kernel(
    const float* __restrict__ x, const float* __restrict__ wts,
    const float* __restrict__ bia, const float* __restrict__ cen,
    float* __restrict__ out, float* __restrict__ bkt, int write_bkt)
{
    const int lane = threadIdx.x;
    const long long base_row = (long long)blockIdx.x * RR;

    // ---- load x: 4 rows x 24 floats/lane as 6 interleaved 16B chunks (coalesced) ----
    u64 xp[RR][2 * NJ];
    float S[RR], Q[RR];
    {
        u64 red[4];   // {sum01, sum23, sq01, sq23} packed row-pairs
        float sm[RR], sq[RR];
        #pragma unroll
        for (int r = 0; r < RR; r++) {
            const ulonglong2* xr = (const ulonglong2*)(x + (base_row + r) * D_DIM) + lane;
            #pragma unroll
            for (int j = 0; j < NJ; j++) {
                ulonglong2 A = xr[j * 32];     // stride 512B between chunks
                xp[r][2 * j] = A.x; xp[r][2 * j + 1] = A.y;
            }
            u64 s2 = add2(add2(add2(xp[r][0], xp[r][1]), add2(xp[r][2], xp[r][3])),
                          add2(add2(xp[r][4], xp[r][5]), add2(xp[r][6], xp[r][7])));
            s2 = add2(s2, add2(add2(xp[r][8], xp[r][9]), add2(xp[r][10], xp[r][11])));
            u64 qa = mul2(xp[r][0], xp[r][0]);
            u64 qb = mul2(xp[r][1], xp[r][1]);
            #pragma unroll
            for (int j = 2; j < 12; j += 2) {
                qa = fma2(xp[r][j], xp[r][j], qa);
                qb = fma2(xp[r][j + 1], xp[r][j + 1], qb);
            }
            u64 q2 = add2(qa, qb);
            float2 ts = unpk(s2), tq = unpk(q2);
            sm[r] = ts.x + ts.y;
            sq[r] = tq.x + tq.y;
        }
        red[0] = pack2(sm[0], sm[1]); red[1] = pack2(sm[2], sm[3]);
        red[2] = pack2(sq[0], sq[1]); red[3] = pack2(sq[2], sq[3]);
        #pragma unroll
        for (int o = 16; o > 0; o >>= 1) {
            #pragma unroll
            for (int i = 0; i < 4; i++)
                red[i] = add2(red[i], __shfl_xor_sync(0xffffffffu, red[i], o));
        }
        float2 a = unpk(red[0]), b = unpk(red[1]), c = unpk(red[2]), d = unpk(red[3]);
        S[0] = a.x; S[1] = a.y; S[2] = b.x; S[3] = b.y;
        Q[0] = c.x; Q[1] = c.y; Q[2] = d.x; Q[3] = d.y;
    }

    // ---- k-loop: 16 centroids, dot per row, butterfly reduce, incremental argmin ----
    float best[RR];
    int   sel[RR];
    #pragma unroll
    for (int r = 0; r < RR; r++) { best[r] = 3.4e38f; sel[r] = 0; }

    #pragma unroll 4
    for (int k = 0; k < K_CL; k++) {
        const ulonglong2* cr = (const ulonglong2*)(cen + k * D_DIM) + lane;
        u64 cp[2 * NJ];
        #pragma unroll
        for (int j = 0; j < NJ; j++) {
            ulonglong2 C = cr[j * 32];
            cp[2 * j] = C.x; cp[2 * j + 1] = C.y;
        }
        float c2k = g_c2[k];      // uniform broadcast load (L1-hot)
        float d[RR];
        #pragma unroll
        for (int r = 0; r < RR; r++) {
            u64 aa = mul2(xp[r][0], cp[0]);
            u64 ab = mul2(xp[r][1], cp[1]);
            #pragma unroll
            for (int j = 2; j < 12; j += 2) {
                aa = fma2(xp[r][j], cp[j], aa);
                ab = fma2(xp[r][j + 1], cp[j + 1], ab);
            }
            float2 t = unpk(add2(aa, ab));
            d[r] = t.x + t.y;
        }
        u64 d01 = pack2(d[0], d[1]);
        u64 d23 = pack2(d[2], d[3]);
        #pragma unroll
        for (int o = 16; o > 0; o >>= 1) {
            d01 = add2(d01, __shfl_xor_sync(0xffffffffu, d01, o));
            d23 = add2(d23, __shfl_xor_sync(0xffffffffu, d23, o));
        }
        float2 t0 = unpk(d01), t1 = unpk(d23);
        float dd[RR] = {t0.x, t0.y, t1.x, t1.y};
        #pragma unroll
        for (int r = 0; r < RR; r++) {
            float dist = Q[r] - 2.0f * dd[r] + c2k;   // same formula as reference
            if (dist < best[r]) { best[r] = dist; sel[r] = k; }  // strict < = first-min
        }
    }

    // ---- epilogue: per-row stats + gathered affine, fully coalesced 16B stores ----
    #pragma unroll
    for (int r = 0; r < RR; r++) {
        float m = S[r] * (1.0f / D_DIM);
        float var = Q[r] * (1.0f / D_DIM) - m * m;
        float rstd = rsqrtf(var + 1e-5f);
        u64 nm = pack2(-m, -m);
        u64 rs = pack2(rstd, rstd);

        const ulonglong2* wr = (const ulonglong2*)(wts + sel[r] * D_DIM) + lane;
        const ulonglong2* br = (const ulonglong2*)(bia + sel[r] * D_DIM) + lane;
        ulonglong2* orow = (ulonglong2*)(out + (base_row + r) * D_DIM) + lane;
        #pragma unroll
        for (int j = 0; j < NJ; j++) {
            ulonglong2 W = wr[j * 32];
            ulonglong2 B = br[j * 32];
            u64 n0 = mul2(add2(xp[r][2 * j], nm), rs);
            u64 n1 = mul2(add2(xp[r][2 * j + 1], nm), rs);
            orow[j * 32] = make_ulonglong2(fma2(n0, W.x, B.x), fma2(n1, W.y, B.y));
        }
        if (write_bkt && lane == 0) bkt[base_row + r] = (float)sel[r];
    }
}

extern "C" void kernel_launch(void* const* d_in, const int* in_sizes, int n_in,
                              void* d_out, int out_size) {
    const float* x = (const float*)d_in[0];   // [B,S,D] f32
    const float* w = (const float*)d_in[1];   // [K,D]
    const float* b = (const float*)d_in[2];   // [K,D]
    const float* c = (const float*)d_in[3];   // [K,D]
    float* out = (float*)d_out;

    int rows = in_sizes[0] / D_DIM;           // 32768
    int wb = (out_size >= rows * D_DIM + rows) ? 1 : 0;
    float* bkt = out + (size_t)rows * D_DIM;

    c2_kernel<<<1, 512>>>(c);
    sln_kernel<<<rows / RR, 32>>>(x, w, b, c, out, bkt, wb);
}